// round 6
// baseline (speedup 1.0000x reference)
#include <cuda_runtime.h>
#include <cuda_bf16.h>

#define NN 50000
#define NE 800000
#define D  64
#define WPAD 68
#define NODES_PER_BLK 16

// Scratch (allocations are forbidden; __device__ globals are the sanctioned path)
__device__ __align__(16) float g_msgs[NN * D];     // x @ W_msg^T + b_msg
__device__ __align__(16) float g_summed[NN * D];   // scatter-sum accumulator
__device__ int   g_counts[NN];                     // in-degree

// ---------------------------------------------------------------------------
// Kernel 1: zero the accumulators (graph replays require re-zeroing each call)
// ---------------------------------------------------------------------------
__global__ void zero_kernel() {
    int gid = blockIdx.x * blockDim.x + threadIdx.x;
    if (gid < NN * D / 4) {
        reinterpret_cast<float4*>(g_summed)[gid] = make_float4(0.f, 0.f, 0.f, 0.f);
    }
    if (gid < NN) g_counts[gid] = 0;
}

// ---------------------------------------------------------------------------
// Kernel 2: fused dual GEMM.
//   g_msgs = x @ Wm^T + bm      (feeds the scatter)
//   out    = x @ Ws^T + bs      (self projection, written straight to d_out)
// Block = 256 threads, 16 nodes. W held transposed in smem as [k][d] (pad 68
// floats/row -> float4-aligned, conflict-free). Thread = (node, 4 out dims):
// per k-step: 1 broadcast LDS (x) + 2x LDS.128 (W) + 8 FFMA.
// ---------------------------------------------------------------------------
__global__ __launch_bounds__(256) void dual_gemm_kernel(
    const float* __restrict__ x,
    const float* __restrict__ Wm, const float* __restrict__ bm,
    const float* __restrict__ Ws, const float* __restrict__ bs,
    float* __restrict__ out)
{
    __shared__ float wm_sh[D * WPAD];
    __shared__ float ws_sh[D * WPAD];
    __shared__ float x_sh[NODES_PER_BLK * WPAD];

    const int t = threadIdx.x;
    const int nbase = blockIdx.x * NODES_PER_BLK;

    // Load both W matrices transposed: Wsh[k][d] = W[d][k]
    for (int i = t; i < D * D; i += 256) {
        int d = i >> 6;
        int k = i & 63;
        wm_sh[k * WPAD + d] = Wm[i];
        ws_sh[k * WPAD + d] = Ws[i];
    }
    // Load x tile (16 nodes x 64) via float4
    {
        int node = t >> 4;
        int c4   = (t & 15) * 4;
        float4 v = *reinterpret_cast<const float4*>(&x[(nbase + node) * D + c4]);
        *reinterpret_cast<float4*>(&x_sh[node * WPAD + c4]) = v;
    }
    __syncthreads();

    const int node = t >> 4;        // 0..15
    const int dq   = (t & 15) * 4;  // output dim quad

    float4 am = make_float4(0.f, 0.f, 0.f, 0.f);
    float4 av = make_float4(0.f, 0.f, 0.f, 0.f);

#pragma unroll
    for (int k = 0; k < D; ++k) {
        float xv = x_sh[node * WPAD + k];
        float4 w1 = *reinterpret_cast<const float4*>(&wm_sh[k * WPAD + dq]);
        am.x = fmaf(xv, w1.x, am.x);
        am.y = fmaf(xv, w1.y, am.y);
        am.z = fmaf(xv, w1.z, am.z);
        am.w = fmaf(xv, w1.w, am.w);
        float4 w2 = *reinterpret_cast<const float4*>(&ws_sh[k * WPAD + dq]);
        av.x = fmaf(xv, w2.x, av.x);
        av.y = fmaf(xv, w2.y, av.y);
        av.z = fmaf(xv, w2.z, av.z);
        av.w = fmaf(xv, w2.w, av.w);
    }

    float4 bmv = *reinterpret_cast<const float4*>(&bm[dq]);
    float4 bsv = *reinterpret_cast<const float4*>(&bs[dq]);
    am.x += bmv.x; am.y += bmv.y; am.z += bmv.z; am.w += bmv.w;
    av.x += bsv.x; av.y += bsv.y; av.z += bsv.z; av.w += bsv.w;

    const int o = (nbase + node) * D + dq;
    *reinterpret_cast<float4*>(&g_msgs[o]) = am;
    *reinterpret_cast<float4*>(&out[o])    = av;
}

// ---------------------------------------------------------------------------
// Kernel 3: edge scatter. 64 threads per edge, ONE scalar float per thread.
// FIX vs R1-R3: edge_index is int32 (JAX silently downgrades int64 with x64
// disabled). Reading it as long long produced garbage node ids -> atomics at
// wild generic addresses -> cudaErrorInvalidAddressSpace (717).
// Indices are clamped as trap insurance (free when valid, warp-uniform).
// Warp = 32 dims of one edge: ei loads warp-uniform, g_msgs read and
// g_summed atomics fully coalesced. Both arrays are L2-resident.
// ---------------------------------------------------------------------------
__global__ __launch_bounds__(256) void scatter_kernel(
    const int* __restrict__ ei)
{
    int gid = blockIdx.x * 256 + threadIdx.x;   // NE*64 = 51.2M threads
    int e = gid >> 6;          // edge id
    int d = gid & 63;          // feature dim
    int r = __ldg(&ei[e]);           // source node (warp-uniform)
    int c = __ldg(&ei[NE + e]);      // destination node (warp-uniform)
    r = min(max(r, 0), NN - 1);
    c = min(max(c, 0), NN - 1);

    float v = __ldg(&g_msgs[r * D + d]);
    atomicAdd(&g_summed[c * D + d], v);
    if (d == 0) {
        atomicAdd(&g_counts[c], 1);
    }
}

// ---------------------------------------------------------------------------
// Kernel 4: out += summed / max(count, 1)
// ---------------------------------------------------------------------------
__global__ __launch_bounds__(256) void finalize_kernel(float* __restrict__ out) {
    int gid = blockIdx.x * 256 + threadIdx.x;   // NN*16 threads
    if (gid >= NN * 16) return;
    int node = gid >> 4;
    int ch   = (gid & 15) * 4;
    float cnt = (float)g_counts[node];
    float inv = 1.0f / fmaxf(cnt, 1.0f);
    float4 s = *reinterpret_cast<const float4*>(&g_summed[node * D + ch]);
    float4 o = *reinterpret_cast<const float4*>(&out[node * D + ch]);
    o.x = fmaf(s.x, inv, o.x);
    o.y = fmaf(s.y, inv, o.y);
    o.z = fmaf(s.z, inv, o.z);
    o.w = fmaf(s.w, inv, o.w);
    *reinterpret_cast<float4*>(&out[node * D + ch]) = o;
}

// ---------------------------------------------------------------------------
extern "C" void kernel_launch(void* const* d_in, const int* in_sizes, int n_in,
                              void* d_out, int out_size)
{
    const float* x   = (const float*)d_in[0];
    const int*   ei  = (const int*)d_in[1];    // int32! (JAX x64-disabled)
    const float* Wm  = (const float*)d_in[2];
    const float* bm  = (const float*)d_in[3];
    const float* Ws  = (const float*)d_in[4];
    const float* bs  = (const float*)d_in[5];
    float*       out = (float*)d_out;

    (void)in_sizes; (void)n_in; (void)out_size;

    // 1) zero accumulators: NN*D/4 = 800000 float4 stores
    zero_kernel<<<(NN * D / 4 + 255) / 256, 256>>>();

    // 2) dual GEMM: 50000 / 16 = 3125 blocks
    dual_gemm_kernel<<<NN / NODES_PER_BLK, 256>>>(x, Wm, bm, Ws, bs, out);

    // 3) scatter: NE*64 / 256 = 200000 blocks
    scatter_kernel<<<NE * 64 / 256, 256>>>(ei);

    // 4) finalize: NN*16 / 256 = 3125 blocks
    finalize_kernel<<<(NN * 16 + 255) / 256, 256>>>(out);
}